// round 2
// baseline (speedup 1.0000x reference)
#include <cuda_runtime.h>
#include <math.h>

#define HWN   16384
#define CC    256
#define BATCH 4
#define CHW   (CC*HWN)
#define SPLITS 8
#define SLAB  (HWN/SPLITS)

// ---------------- scratch (static __device__, no allocations) ----------------
__device__ __align__(16) float d_Sx[BATCH*CC];
__device__ __align__(16) float d_Sxx[BATCH*CC];
__device__ __align__(16) float d_m[BATCH*CC];
__device__ __align__(16) float d_a[BATCH*CC];
__device__ __align__(16) float d_wa[BATCH*CC];
__device__ __align__(16) float d_rp[BATCH*CC];
__device__ __align__(16) float d_Wq[CC*CC];
__device__ __align__(16) float d_Wk[CC*CC];
__device__ __align__(16) float d_Wv[CC*CC];
__device__ __align__(16) float d_btq[CC];
__device__ __align__(16) float d_btk[CC];
__device__ __align__(16) float d_btv[CC];
__device__ __align__(16) float d_Gpart[BATCH*SPLITS*CC*CC];   // 8 MB
__device__ __align__(16) float d_G[BATCH*CC*CC];
__device__ __align__(16) float d_U[BATCH*CC*CC];
__device__ __align__(16) float d_pq[BATCH*CC];
__device__ __align__(16) float d_pk[BATCH*CC];
__device__ __align__(16) float d_sc[BATCH*64*16];
__device__ __align__(16) float d_Smx[BATCH*64*16];
__device__ __align__(16) float d_T[BATCH*CC*CC];
__device__ __align__(16) float d_tv[BATCH*CC];
__device__ __align__(16) float d_E[BATCH*CC*CC];
__device__ __align__(16) float d_F[BATCH*CC*CC];
__device__ __align__(16) float d_g[BATCH*CC];

// ---------------- 1) per-(b,c) sums of x ----------------
__global__ void stats_kernel(const float* __restrict__ x) {
    int bc = blockIdx.x;
    const float4* p = (const float4*)(x + (size_t)bc * HWN);
    float s = 0.f, s2 = 0.f;
    for (int i = threadIdx.x; i < HWN/4; i += 256) {
        float4 v = p[i];
        s  += v.x + v.y + v.z + v.w;
        s2 += v.x*v.x + v.y*v.y + v.z*v.z + v.w*v.w;
    }
    for (int o = 16; o; o >>= 1) {
        s  += __shfl_down_sync(0xffffffffu, s, o);
        s2 += __shfl_down_sync(0xffffffffu, s2, o);
    }
    __shared__ float sh[8][2];
    int w = threadIdx.x >> 5, l = threadIdx.x & 31;
    if (l == 0) { sh[w][0] = s; sh[w][1] = s2; }
    __syncthreads();
    if (threadIdx.x == 0) {
        float S = 0.f, S2 = 0.f;
        for (int i = 0; i < 8; i++) { S += sh[i][0]; S2 += sh[i][1]; }
        d_Sx[bc] = S; d_Sxx[bc] = S2;
    }
}

// ---------------- 2) pack qkv rows into head-contiguous Wq/Wk/Wv + fold gn_bias ----------------
// qkv channel layout: o = h*12 + j ; j in [0,4)=q, [4,8)=k, [8,12)=v. packed p = h*4+d.
__global__ void pack_kernel(const float* __restrict__ qkvw,
                            const float* __restrict__ qkvb,
                            const float* __restrict__ gnb) {
    int rid = blockIdx.x * 128 + threadIdx.x;          // 0..767
    if (rid >= 768) return;
    int sel = rid / 256;
    int p   = rid % 256;
    int h = p >> 2, dd = p & 3;
    int src = h * 12 + sel * 4 + dd;
    const float* wrow = qkvw + src * 256;
    float* dst = (sel == 0 ? d_Wq : (sel == 1 ? d_Wk : d_Wv)) + p * 256;
    float dot = 0.f;
    for (int c = 0; c < 256; c++) {
        float w = wrow[c];
        dst[c] = w;
        dot += w * gnb[c];
    }
    float bt = qkvb[src] + dot;
    if (sel == 0) d_btq[p] = bt; else if (sel == 1) d_btk[p] = bt; else d_btv[p] = bt;
}

// ---------------- 3) group stats -> per-channel mean/scale, row sums ----------------
__global__ void groupstats_kernel(const float* __restrict__ gnw) {
    int t = threadIdx.x;               // 0..127 = (b,g)
    if (t >= 128) return;
    int b = t >> 5, g = t & 31;
    float s = 0.f, s2 = 0.f;
    for (int c8 = 0; c8 < 8; c8++) {
        int idx = b * 256 + g * 8 + c8;
        s += d_Sx[idx]; s2 += d_Sxx[idx];
    }
    const float n = 8.f * (float)HWN;      // 131072
    float mean = s / n;
    float var  = (s2 - n * mean * mean) / (n - 1.f);
    float a = rsqrtf(var + 1e-5f);
    for (int c8 = 0; c8 < 8; c8++) {
        int c = g * 8 + c8;
        int idx = b * 256 + c;
        d_m[idx] = mean;
        d_a[idx] = a;
        float wa = gnw[c] * a;
        d_wa[idx] = wa;
        d_rp[idx] = wa * (d_Sx[idx] - (float)HWN * mean);
    }
}

// ---------------- 4) Gram partials: Gx = x xT (per batch, split-K over n) ----------------
__global__ void gram_kernel(const float* __restrict__ x) {
    int b = blockIdx.z, split = blockIdx.y, t = blockIdx.x;
    int ti = t >> 2, tj = t & 3;
    const float* xb = x + (size_t)b * CHW;
    int i0 = ti * 64, j0 = tj * 64;
    __shared__ float As[16][64];
    __shared__ float Bs[16][64];
    int tid = threadIdx.x;
    int tx = tid & 15, ty = tid >> 4;
    int lr = tid >> 2, ls = tid & 3;
    float acc[4][4] = {};
    int kbase = split * SLAB;
    for (int k0 = kbase; k0 < kbase + SLAB; k0 += 16) {
        float4 av = *(const float4*)&xb[(size_t)(i0 + lr) * HWN + k0 + ls * 4];
        As[ls*4+0][lr] = av.x; As[ls*4+1][lr] = av.y; As[ls*4+2][lr] = av.z; As[ls*4+3][lr] = av.w;
        float4 bv = *(const float4*)&xb[(size_t)(j0 + lr) * HWN + k0 + ls * 4];
        Bs[ls*4+0][lr] = bv.x; Bs[ls*4+1][lr] = bv.y; Bs[ls*4+2][lr] = bv.z; Bs[ls*4+3][lr] = bv.w;
        __syncthreads();
#pragma unroll
        for (int kk = 0; kk < 16; kk++) {
            float4 a4 = *(const float4*)&As[kk][ty * 4];
            float4 b4 = *(const float4*)&Bs[kk][tx * 4];
            float avv[4] = {a4.x, a4.y, a4.z, a4.w};
            float bvv[4] = {b4.x, b4.y, b4.z, b4.w};
#pragma unroll
            for (int i = 0; i < 4; i++)
#pragma unroll
                for (int j = 0; j < 4; j++)
                    acc[i][j] += avv[i] * bvv[j];
        }
        __syncthreads();
    }
    float* gp = d_Gpart + (size_t)(b * SPLITS + split) * 65536;
#pragma unroll
    for (int i = 0; i < 4; i++) {
        int row = i0 + ty * 4 + i;
        float4 v; v.x = acc[i][0]; v.y = acc[i][1]; v.z = acc[i][2]; v.w = acc[i][3];
        *(float4*)&gp[row * 256 + j0 + tx * 4] = v;
    }
}

// ---------------- 5) reduce partials + GN corrections -> G' ----------------
__global__ void reduceG_kernel() {
    int e = blockIdx.x * 256 + threadIdx.x;    // 0..262143
    int b = e >> 16;
    int ij = e & 65535;
    int i = ij >> 8, j = ij & 255;
    float sum = 0.f;
    size_t base = (size_t)b * SPLITS * 65536 + ij;
    for (int s = 0; s < SPLITS; s++) sum += d_Gpart[base + (size_t)s * 65536];
    int bi = b * 256 + i, bj = b * 256 + j;
    float g = d_wa[bi] * d_wa[bj] *
              (sum - d_m[bi] * d_Sx[bj] - d_m[bj] * d_Sx[bi] + (float)HWN * d_m[bi] * d_m[bj]);
    d_G[b * 65536 + ij] = g;
}

// ---------------- generic 64x64-tile GEMM (M=256, K=256) ----------------
// MODE 0: U = Wq @ G'        (N=256)
// MODE 1: E = out_w @ T      (N=256)
// MODE 2: out = F @ x + g + x (N=16384, epilogue)
template<int MODE>
__global__ void gemm64(const float* __restrict__ Aext,
                       const float* __restrict__ Bext,
                       float* __restrict__ Cext) {
    constexpr int N = (MODE == 2) ? HWN : 256;
    int b = blockIdx.z;
    const float* A; const float* B; float* Cp;
    const float* bias = nullptr; const float* skip = nullptr;
    if (MODE == 0) { A = d_Wq;                 B = d_G + b * 65536;        Cp = d_U + b * 65536; }
    else if (MODE == 1) { A = Aext;            B = d_T + b * 65536;        Cp = d_E + b * 65536; }
    else { A = d_F + b * 65536; B = Bext + (size_t)b * CHW; Cp = Cext + (size_t)b * CHW;
           bias = d_g + b * 256; skip = B; }

    __shared__ float As[16][64];
    __shared__ float Bs[16][64];
    int m0 = blockIdx.x * 64, n0 = blockIdx.y * 64;
    int tid = threadIdx.x;
    int tx = tid & 15, ty = tid >> 4;
    int ar = tid >> 2, asg = tid & 3;
    int br = tid >> 4, bc = tid & 15;
    float acc[4][4] = {};
    for (int k0 = 0; k0 < 256; k0 += 16) {
        float4 av = *(const float4*)&A[(m0 + ar) * 256 + k0 + asg * 4];
        As[asg*4+0][ar] = av.x; As[asg*4+1][ar] = av.y; As[asg*4+2][ar] = av.z; As[asg*4+3][ar] = av.w;
        float4 bv = *(const float4*)&B[(size_t)(k0 + br) * N + n0 + bc * 4];
        *(float4*)&Bs[br][bc * 4] = bv;
        __syncthreads();
#pragma unroll
        for (int kk = 0; kk < 16; kk++) {
            float4 a4 = *(const float4*)&As[kk][ty * 4];
            float4 b4 = *(const float4*)&Bs[kk][tx * 4];
            float avv[4] = {a4.x, a4.y, a4.z, a4.w};
            float bvv[4] = {b4.x, b4.y, b4.z, b4.w};
#pragma unroll
            for (int i = 0; i < 4; i++)
#pragma unroll
                for (int j = 0; j < 4; j++)
                    acc[i][j] += avv[i] * bvv[j];
        }
        __syncthreads();
    }
#pragma unroll
    for (int i = 0; i < 4; i++) {
        int m = m0 + ty * 4 + i;
        float4 v; v.x = acc[i][0]; v.y = acc[i][1]; v.z = acc[i][2]; v.w = acc[i][3];
        if (MODE == 2) {
            float bi = bias[m];
            float4 sk = *(const float4*)&skip[(size_t)m * N + n0 + tx * 4];
            v.x += bi + sk.x; v.y += bi + sk.y; v.z += bi + sk.z; v.w += bi + sk.w;
        }
        *(float4*)&Cp[(size_t)m * N + n0 + tx * 4] = v;
    }
}

// ---------------- 6) p-vectors: pq/pk = Wq/Wk @ r' ----------------
__global__ void pvec_kernel() {
    int rid = blockIdx.x * 128 + threadIdx.x;   // 0..2047
    if (rid >= 2048) return;
    int b = rid / 512;
    int q = rid % 512;
    int sel = q / 256, p = q % 256;
    const float* w = (sel ? d_Wk : d_Wq) + p * 256;
    const float* r = d_rp + b * 256;
    float s = 0.f;
    for (int c = 0; c < 256; c++) s += w[c] * r[c];
    (sel ? d_pk : d_pq)[b * 256 + p] = s;
}

// ---------------- 7) raw scores: (U Wk^T + bias corrections)/2 ----------------
__global__ void scores_kernel() {
    int bi = blockIdx.x;
    int b = bi >> 6, h = bi & 63;
    int tid = threadIdx.x;
    int pair = tid >> 4, l = tid & 15;
    int dd = pair >> 2, ee = pair & 3;
    int pU = h * 4 + dd, pK = h * 4 + ee;
    const float* u  = d_U + (size_t)b * 65536 + pU * 256;
    const float* wk = d_Wk + pK * 256;
    float s = 0.f;
    for (int c = l; c < 256; c += 16) s += u[c] * wk[c];
    for (int o = 8; o; o >>= 1) s += __shfl_down_sync(0xffffffffu, s, o, 16);
    if (l == 0) {
        s += d_pq[b * 256 + pU] * d_btk[pK]
           + d_btq[pU] * d_pk[b * 256 + pK]
           + (float)HWN * d_btq[pU] * d_btk[pK];
        d_sc[(b * 64 + h) * 16 + pair] = 0.5f * s;
    }
}

// ---------------- 8) softmax over heads axis ----------------
__global__ void softmax_kernel() {
    int b = blockIdx.x;
    int w = threadIdx.x >> 5;     // pair 0..15
    int l = threadIdx.x & 31;     // heads l and l+32
    float v0 = d_sc[((b * 64 + l) << 4) + w];
    float v1 = d_sc[((b * 64 + l + 32) << 4) + w];
    float mx = fmaxf(v0, v1);
    for (int o = 16; o; o >>= 1) mx = fmaxf(mx, __shfl_xor_sync(0xffffffffu, mx, o));
    float e0 = expf(v0 - mx), e1 = expf(v1 - mx);
    float s = e0 + e1;
    for (int o = 16; o; o >>= 1) s += __shfl_xor_sync(0xffffffffu, s, o);
    d_Smx[((b * 64 + l) << 4) + w] = e0 / s;
    d_Smx[((b * 64 + l + 32) << 4) + w] = e1 / s;
}

// ---------------- 9) T = BlockDiag(S) Wv diag(gnw), tv = BD(S) btv ----------------
__global__ void t_kernel(const float* __restrict__ gnw) {
    int bi = blockIdx.x;
    int b = bi >> 6, h = bi & 63;
    int c = threadIdx.x;
    __shared__ float Ssh[16];
    if (c < 16) Ssh[c] = d_Smx[(b * 64 + h) * 16 + c];
    __syncthreads();
    float w0 = d_Wv[(h*4+0)*256 + c];
    float w1 = d_Wv[(h*4+1)*256 + c];
    float w2 = d_Wv[(h*4+2)*256 + c];
    float w3 = d_Wv[(h*4+3)*256 + c];
    float gc = gnw[c];
#pragma unroll
    for (int dd = 0; dd < 4; dd++) {
        float s = Ssh[dd*4+0]*w0 + Ssh[dd*4+1]*w1 + Ssh[dd*4+2]*w2 + Ssh[dd*4+3]*w3;
        d_T[((size_t)b * 256 + h * 4 + dd) * 256 + c] = gc * s;
    }
    if (c < 4) {
        float tv = 0.f;
        for (int e = 0; e < 4; e++) tv += Ssh[c * 4 + e] * d_btv[h * 4 + e];
        d_tv[b * 256 + h * 4 + c] = tv;
    }
}

// ---------------- 10) fold: F = E diag(a), g = out_b + out_w tv - F m ----------------
__global__ void fold_kernel(const float* __restrict__ outw,
                            const float* __restrict__ outb) {
    int b = blockIdx.x;
    int o = threadIdx.x;
    const float* ow = outw + o * 256;
    float e = outb[o];
    for (int p = 0; p < 256; p++) e += ow[p] * d_tv[b * 256 + p];
    float gacc = 0.f;
    for (int c = 0; c < 256; c++) {
        int idx = (b * 256 + o) * 256 + c;
        float f = d_E[idx] * d_a[b * 256 + c];
        d_F[idx] = f;
        gacc += f * d_m[b * 256 + c];
    }
    d_g[b * 256 + o] = e - gacc;
}

// ---------------- launch ----------------
extern "C" void kernel_launch(void* const* d_in, const int* in_sizes, int n_in,
                              void* d_out, int out_size) {
    const float* x    = (const float*)d_in[0];
    const float* gnw  = (const float*)d_in[1];
    const float* gnb  = (const float*)d_in[2];
    const float* qkvw = (const float*)d_in[3];
    const float* qkvb = (const float*)d_in[4];
    const float* outw = (const float*)d_in[5];
    const float* outb = (const float*)d_in[6];
    float* out = (float*)d_out;

    stats_kernel<<<BATCH * CC, 256>>>(x);
    pack_kernel<<<6, 128>>>(qkvw, qkvb, gnb);
    groupstats_kernel<<<1, 128>>>(gnw);
    gram_kernel<<<dim3(16, SPLITS, BATCH), 256>>>(x);
    reduceG_kernel<<<1024, 256>>>();
    gemm64<0><<<dim3(4, 4, BATCH), 256>>>(nullptr, nullptr, nullptr);
    pvec_kernel<<<16, 128>>>();
    scores_kernel<<<BATCH * 64, 256>>>();
    softmax_kernel<<<BATCH, 512>>>();
    t_kernel<<<BATCH * 64, 256>>>(gnw);
    gemm64<1><<<dim3(4, 4, BATCH), 256>>>(outw, nullptr, nullptr);
    fold_kernel<<<BATCH, 256>>>(outw, outb);
    gemm64<2><<<dim3(4, HWN / 64, BATCH), 256>>>(nullptr, x, out);
}